// round 3
// baseline (speedup 1.0000x reference)
#include <cuda_runtime.h>
#include <cstdint>
#include <float.h>

// Sparsemax, persistent CTAs, register-resident rows with software prefetch.
//
// Exact algorithm: tau >= rowmax - 1 always, so the support is contained in
// C = { x > rowmax - 1 } (tiny for Gaussian rows). Gather C into smem, solve
// exactly with Newton/Michelot iteration (redundantly on every warp -> no
// broadcast barrier), emit max(x - tau, 0).
//
// Row data lives in registers: loaded once (__ldcs), next row prefetched into
// a second register set before the compute phases so the LDG latency hides
// behind them. Only 2 __syncthreads per row; max-reduce via shared atomicMax
// on a monotone uint encoding. Per-iteration accumulators are parity-slotted
// so their reset overlaps the pipeline instead of needing a third barrier.

#define THREADS 512
#define COLS    8192
#define CAP     512
#define GRID    296        // 2 CTAs per SM x 148 SMs, 13-14 rows per CTA

// monotone float->uint encoding (order-preserving for atomicMax)
__device__ __forceinline__ unsigned encf(float f) {
    unsigned s = __float_as_uint(f);
    return (s & 0x80000000u) ? ~s : (s | 0x80000000u);
}
__device__ __forceinline__ float decf(unsigned u) {
    return __uint_as_float((u & 0x80000000u) ? (u & 0x7fffffffu) : ~u);
}

__global__ __launch_bounds__(THREADS, 2)
void sparsemax_reg(const float* __restrict__ x, float* __restrict__ out, int rows)
{
    __shared__ unsigned s_maxu[2];     // parity-slotted row-max accumulator
    __shared__ int      s_cnt[2];      // parity-slotted candidate count
    __shared__ float    s_cand[CAP];
    __shared__ float    s_red[32];     // fallback scratch
    __shared__ float    s_tau;         // fallback scratch
    __shared__ int      s_done;        // fallback scratch

    const int tid  = threadIdx.x;
    const int lane = tid & 31;

    if (tid == 0) { s_maxu[0] = 0u; s_maxu[1] = 0u; s_cnt[0] = 0; s_cnt[1] = 0; }
    __syncthreads();

    const long long stride = gridDim.x;
    const long long j0 = blockIdx.x;
    if (j0 >= rows) return;

    // prologue: load first row into registers
    float4 v[4];
    {
        const float4* xin = reinterpret_cast<const float4*>(x + j0 * COLS);
#pragma unroll
        for (int i = 0; i < 4; ++i) v[i] = __ldcs(xin + tid + i * THREADS);
    }

    int p = 0;
#pragma unroll 1
    for (long long j = j0; j < rows; j += stride) {
        const long long jn = j + stride;

        // ---- prefetch next row into second register set (latency hidden
        //      behind this row's compute; scoreboard-waited only at rotation)
        float4 w[4];
        if (jn < rows) {
            const float4* xn = reinterpret_cast<const float4*>(x + jn * COLS);
#pragma unroll
            for (int i = 0; i < 4; ++i) w[i] = __ldcs(xn + tid + i * THREADS);
        }

        // ---- row max: warp shfl-reduce + one shared atomicMax ----
        float m = -FLT_MAX;
#pragma unroll
        for (int i = 0; i < 4; ++i)
            m = fmaxf(m, fmaxf(fmaxf(v[i].x, v[i].y), fmaxf(v[i].z, v[i].w)));
#pragma unroll
        for (int o = 16; o > 0; o >>= 1) m = fmaxf(m, __shfl_xor_sync(0xffffffffu, m, o));
        if (lane == 0) atomicMax(&s_maxu[p], encf(m));
        __syncthreads();                                   // barrier 1
        if (tid == 0) { s_maxu[p ^ 1] = 0u; s_cnt[p ^ 1] = 0; }  // reset other slot
        const float thresh = decf(s_maxu[p]) - 1.0f;       // tau >= thresh

        // ---- gather candidates > thresh from registers ----
#pragma unroll
        for (int i = 0; i < 4; ++i) {
            const float e[4] = {v[i].x, v[i].y, v[i].z, v[i].w};
#pragma unroll
            for (int k = 0; k < 4; ++k) {
                if (e[k] > thresh) {
                    int q = atomicAdd(&s_cnt[p], 1);
                    if (q < CAP) s_cand[q] = e[k];
                }
            }
        }
        __syncthreads();                                   // barrier 2
        const int cnt = s_cnt[p];

        float tau;
        if (cnt <= CAP) {
            // ---- exact Newton/Michelot, run redundantly by EVERY warp
            //      (same data -> same tau; no broadcast barrier needed) ----
            float t0 = thresh;
            for (int it = 0; it < 64; ++it) {
                float s = 0.0f, k = 0.0f;
                for (int i = lane; i < cnt; i += 32) {
                    float c = s_cand[i];
                    if (c > t0) { s += c; k += 1.0f; }
                }
#pragma unroll
                for (int o = 16; o > 0; o >>= 1) {
                    s += __shfl_xor_sync(0xffffffffu, s, o);
                    k += __shfl_xor_sync(0xffffffffu, k, o);
                }
                if (k < 0.5f) break;          // safety (cannot happen in theory)
                float nt = (s - 1.0f) / k;
                if (nt == t0) break;          // exact fixed point
                t0 = nt;
            }
            tau = t0;
        } else {
            // ---- fallback: block-wide Michelot over register row (uniform
            //      branch, internally barriered; never expected to trigger) ----
            float t0 = thresh;
            for (int it = 0; it < 64; ++it) {
                float s = 0.0f, k = 0.0f;
#pragma unroll
                for (int i = 0; i < 4; ++i) {
                    const float e[4] = {v[i].x, v[i].y, v[i].z, v[i].w};
#pragma unroll
                    for (int q = 0; q < 4; ++q)
                        if (e[q] > t0) { s += e[q]; k += 1.0f; }
                }
#pragma unroll
                for (int o = 16; o > 0; o >>= 1) {
                    s += __shfl_xor_sync(0xffffffffu, s, o);
                    k += __shfl_xor_sync(0xffffffffu, k, o);
                }
                const int wid = tid >> 5;
                if (lane == 0) { s_red[2 * wid] = s; s_red[2 * wid + 1] = k; }
                __syncthreads();
                if (tid == 0) {
                    float Sx = 0.0f, K = 0.0f;
                    for (int w2 = 0; w2 < 16; ++w2) { Sx += s_red[2 * w2]; K += s_red[2 * w2 + 1]; }
                    float nt = (K < 0.5f) ? t0 : (Sx - 1.0f) / K;
                    s_done = (nt == t0) || (K < 0.5f);
                    s_tau  = nt;
                }
                __syncthreads();
                t0 = s_tau;
                if (s_done) break;
            }
            tau = t0;
        }

        // ---- emit output from registers (streaming stores) ----
        float4* y4 = reinterpret_cast<float4*>(out + j * COLS);
#pragma unroll
        for (int i = 0; i < 4; ++i) {
            float4 r;
            r.x = fmaxf(v[i].x - tau, 0.0f);
            r.y = fmaxf(v[i].y - tau, 0.0f);
            r.z = fmaxf(v[i].z - tau, 0.0f);
            r.w = fmaxf(v[i].w - tau, 0.0f);
            __stcs(y4 + tid + i * THREADS, r);
        }

        // ---- rotate prefetched row into place ----
#pragma unroll
        for (int i = 0; i < 4; ++i) v[i] = w[i];
        p ^= 1;
    }
}

extern "C" void kernel_launch(void* const* d_in, const int* in_sizes, int n_in,
                              void* d_out, int out_size)
{
    const float* x = (const float*)d_in[0];
    float* out     = (float*)d_out;
    const int rows = in_sizes[0] / COLS;
    sparsemax_reg<<<GRID, THREADS>>>(x, out, rows);
}